// round 14
// baseline (speedup 1.0000x reference)
#include <cuda_runtime.h>

// EKF cell: B=262144, N=8, M=4. One thread/batch, one warp/CTA (32 batches).
// Round-14 = round-13 + TIERED prefetch distances:
//   phase-1 inputs (F, state_cov)  prefetched at AHEAD1=512 (~3.7us lead, 8MB)
//   phase-2 inputs (H, pn, mn)     prefetched at AHEAD2=256 (~1.8us lead, 2.5MB)
// R12 (all at 512, 15MB) was slower than R13 (F/P only, 8MB) -> window size
// matters; the tiered scheme L2-stages phase-2 with minimal extra footprint
// so the phase-2 demand TMA (currently ~800cyc DRAM, only ~600 hidden by the
// P'=FPF^T compute) becomes an L2 hit and disappears from the critical path.

#define OFF_P_F4   544       // P padded region base (f4)
#define OFF_MB_FLT 4352      // mbarrier (float offset, 16B aligned)
#define SM_FLOATS  4356
#define TX1 16384u           // F 8192 + P 8192
#define TX2 9984u            // H 4096 + pn 4608 + mn 1280
#define PN_F4 288            // pn base (f4): 288..575
#define MN_F4 576            // mn base (f4): 576..655
#define AHEAD1 512           // phase-1 prefetch distance
#define AHEAD2 256           // phase-2 prefetch distance

__device__ __forceinline__ float psym(const float* t, int i, int j) {
    return (i >= j) ? t[i*(i+1)/2 + j] : t[j*(j+1)/2 + i];
}

__device__ __forceinline__ unsigned sptr(const void* p) {
    return (unsigned)__cvta_generic_to_shared(p);
}

__device__ __forceinline__ void bulk_g2s(unsigned dst, const void* src,
                                         unsigned bytes, unsigned mbar) {
    asm volatile(
        "cp.async.bulk.shared::cluster.global.mbarrier::complete_tx::bytes [%0], [%1], %2, [%3];"
        :: "r"(dst), "l"(src), "r"(bytes), "r"(mbar) : "memory");
}

__device__ __forceinline__ void bulk_s2g(void* dst, unsigned src, unsigned bytes) {
    asm volatile(
        "cp.async.bulk.global.shared::cta.bulk_group [%0], [%1], %2;"
        :: "l"(dst), "r"(src), "r"(bytes) : "memory");
}

__device__ __forceinline__ void l2_prefetch(const void* src, unsigned bytes) {
    asm volatile("cp.async.bulk.prefetch.L2.global [%0], %1;"
                 :: "l"(src), "r"(bytes) : "memory");
}

__device__ __forceinline__ void mbar_wait(unsigned mbar, int parity) {
    asm volatile(
        "{\n\t"
        ".reg .pred P;\n"
        "W%=:\n\t"
        "mbarrier.try_wait.parity.shared.b64 P, [%0], %1;\n\t"
        "@!P bra W%=;\n\t"
        "}"
        :: "r"(mbar), "r"(parity) : "memory");
}

__global__ __launch_bounds__(32, 12) void ekf_kernel(
    const float* __restrict__ g_meas,
    const float* __restrict__ g_state,
    const float* __restrict__ g_cov,
    const float* __restrict__ g_F,
    const float* __restrict__ g_H,
    const float* __restrict__ g_pn,
    const float* __restrict__ g_mn,
    float* __restrict__ o_pred,
    float* __restrict__ o_state,
    float* __restrict__ o_cov,
    int B)
{
    __shared__ __align__(16) float sm[SM_FLOATS];
    float4* s4m = reinterpret_cast<float4*>(sm);

    const int lane = threadIdx.x;
    int wb = blockIdx.x * 32;
    if (wb + 32 > B) wb = B - 32;   // clamp tail: duplicate identical work
    const int b = wb + lane;

    const unsigned smb  = sptr(sm);
    const unsigned mbar = smb + OFF_MB_FLT * 4;

    // ---------- phase 1: TMA F + P (plus tiered L2 prefetch ahead) ----------
    if (lane == 0) {
        asm volatile("mbarrier.init.shared.b64 [%0], 1;" :: "r"(mbar) : "memory");
    }
    __syncwarp();
    if (lane == 0) {
        asm volatile("fence.proxy.async.shared::cta;" ::: "memory");
        asm volatile("mbarrier.arrive.expect_tx.shared.b64 _, [%0], %1;"
                     :: "r"(mbar), "r"(TX1) : "memory");
        bulk_g2s(smb,                  g_F   + (size_t)wb * 64, 8192, mbar);
        bulk_g2s(smb + OFF_P_F4 * 16,  g_cov + (size_t)wb * 64, 8192, mbar);
        // tier 1: phase-1 inputs for the CTA ~3.7us behind us
        int p1 = (blockIdx.x + AHEAD1) * 32;
        if (p1 + 32 <= B) {
            l2_prefetch(g_F   + (size_t)p1 * 64, 8192);
            l2_prefetch(g_cov + (size_t)p1 * 64, 8192);
        }
        // tier 2: phase-2 inputs for the CTA ~1.8us behind us
        int p2 = (blockIdx.x + AHEAD2) * 32;
        if (p2 + 32 <= B) {
            l2_prefetch(g_H  + (size_t)p2 * 32, 4096);
            l2_prefetch(g_pn + (size_t)p2 * 36, 4608);
            l2_prefetch(g_mn + (size_t)p2 * 10, 1280);
        }
    }

    // overlap: small direct loads
    float mea[4], st[8];
    {
        float4 mv = reinterpret_cast<const float4*>(g_meas)[b];
        mea[0] = mv.x; mea[1] = mv.y; mea[2] = mv.z; mea[3] = mv.w;
        const float4* s4 = reinterpret_cast<const float4*>(g_state) + (size_t)b * 2;
        float4 a = s4[0], c = s4[1];
        st[0]=a.x; st[1]=a.y; st[2]=a.z; st[3]=a.w;
        st[4]=c.x; st[5]=c.y; st[6]=c.z; st[7]=c.w;
    }

    mbar_wait(mbar, 0);
    __syncwarp();

    // ---------- pad-repack F and P: stride 16 -> 17 f4 (in place) ----------
    #pragma unroll
    for (int base = OFF_P_F4; base >= 0; base -= OFF_P_F4) {  // P then F
        float4 t[8];
        #pragma unroll
        for (int k = 0; k < 8; k++) t[k] = s4m[base + 256 + lane + 32*k];
        __syncwarp();
        #pragma unroll
        for (int k = 0; k < 8; k++) {
            int g = 256 + lane + 32*k;
            s4m[base + (g >> 4) * 17 + (g & 15)] = t[k];
        }
        __syncwarp();
        #pragma unroll
        for (int k = 0; k < 8; k++) t[k] = s4m[base + lane + 32*k];
        __syncwarp();
        #pragma unroll
        for (int k = 0; k < 8; k++) {
            int g = lane + 32*k;
            s4m[base + (g >> 4) * 17 + (g & 15)] = t[k];
        }
        __syncwarp();
    }

    // ---------- unpack F (64 regs) and P (tri 36 regs) ----------
    float Fm[64];
    #pragma unroll
    for (int v = 0; v < 16; v++) {
        float4 x = s4m[lane * 17 + v];
        Fm[4*v+0] = x.x; Fm[4*v+1] = x.y; Fm[4*v+2] = x.z; Fm[4*v+3] = x.w;
    }
    float Pt[36];
    #pragma unroll
    for (int v = 0; v < 16; v++) {
        float4 x = s4m[OFF_P_F4 + lane * 17 + v];
        float vals[4] = {x.x, x.y, x.z, x.w};
        #pragma unroll
        for (int c = 0; c < 4; c++) {
            int e = 4*v + c, i = e >> 3, j = e & 7;
            if (i >= j) Pt[i*(i+1)/2 + j] = vals[c];
        }
    }
    __syncwarp();   // all lanes done reading F/P smem

    // ---------- phase 2: TMA H / pn / mn into now-dead smem ----------
    if (lane == 0) {
        asm volatile("fence.proxy.async.shared::cta;" ::: "memory");
        asm volatile("mbarrier.arrive.expect_tx.shared.b64 _, [%0], %1;"
                     :: "r"(mbar), "r"(TX2) : "memory");
        bulk_g2s(smb,              g_H  + (size_t)wb * 32, 4096, mbar);
        bulk_g2s(smb + PN_F4 * 16, g_pn + (size_t)wb * 36, 4608, mbar);
        bulk_g2s(smb + MN_F4 * 16, g_mn + (size_t)wb * 10, 1280, mbar);
    }

    // ---- compute overlapped with phase-2 TMA ----
    float ns[8];
    #pragma unroll
    for (int i = 0; i < 8; i++) {
        float a = 0.f;
        #pragma unroll
        for (int j = 0; j < 8; j++) a += Fm[i*8+j] * st[j];
        ns[i] = a;
    }
    // P' = F P F^T (column-strip, lower tri)
    float Pp[36];
    #pragma unroll
    for (int l = 0; l < 8; l++) {
        float g[8];
        #pragma unroll
        for (int j = 0; j < 8; j++) {
            float a = 0.f;
            #pragma unroll
            for (int k = 0; k < 8; k++) a += psym(Pt, j, k) * Fm[l*8+k];
            g[j] = a;
        }
        #pragma unroll
        for (int i = l; i < 8; i++) {
            float a = 0.f;
            #pragma unroll
            for (int j = 0; j < 8; j++) a += Fm[i*8+j] * g[j];
            Pp[i*(i+1)/2 + l] = a;
        }
    }
    // Fm, Pt dead.

    mbar_wait(mbar, 1);
    __syncwarp();

    // ---- repack H: stride 8 -> 9 f4 (in place, top half first) ----
    {
        float4 t[4];
        #pragma unroll
        for (int k = 0; k < 4; k++) t[k] = s4m[128 + lane + 32*k];
        __syncwarp();
        #pragma unroll
        for (int k = 0; k < 4; k++) {
            int g = 128 + lane + 32*k;
            s4m[(g >> 3) * 9 + (g & 7)] = t[k];
        }
        __syncwarp();
        #pragma unroll
        for (int k = 0; k < 4; k++) t[k] = s4m[lane + 32*k];
        __syncwarp();
        #pragma unroll
        for (int k = 0; k < 4; k++) {
            int g = lane + 32*k;
            s4m[(g >> 3) * 9 + (g & 7)] = t[k];
        }
        __syncwarp();
    }

    // ---- P' += Q = Lq Lq^T ----
    {
        float Lq[36];
        #pragma unroll
        for (int v = 0; v < 9; v++) {
            float4 x = s4m[PN_F4 + lane * 9 + v];
            Lq[4*v+0] = x.x; Lq[4*v+1] = x.y; Lq[4*v+2] = x.z; Lq[4*v+3] = x.w;
        }
        #pragma unroll
        for (int i = 0; i < 8; i++) {
            #pragma unroll
            for (int l = 0; l <= i; l++) {
                float a = Pp[i*(i+1)/2 + l];
                #pragma unroll
                for (int k = 0; k <= l; k++)
                    a += Lq[i*(i+1)/2 + k] * Lq[l*(l+1)/2 + k];
                Pp[i*(i+1)/2 + l] = a;
            }
        }
    }

    // ---- H; prediction & residual ----
    float Hm[32];
    #pragma unroll
    for (int v = 0; v < 8; v++) {
        float4 x = s4m[lane * 9 + v];
        Hm[4*v+0] = x.x; Hm[4*v+1] = x.y; Hm[4*v+2] = x.z; Hm[4*v+3] = x.w;
    }
    float pred[4], res[4];
    #pragma unroll
    for (int i = 0; i < 4; i++) {
        float a = 0.f;
        #pragma unroll
        for (int j = 0; j < 8; j++) a += Hm[i*8+j] * ns[j];
        pred[i] = a;
        res[i] = mea[i] - a;
    }

    // ---- PHt = P' @ H^T ----
    float PHt[32];
    #pragma unroll
    for (int i = 0; i < 8; i++) {
        #pragma unroll
        for (int j = 0; j < 4; j++) {
            float a = 0.f;
            #pragma unroll
            for (int k = 0; k < 8; k++) a += psym(Pp, i, k) * Hm[j*8+k];
            PHt[i*4+j] = a;
        }
    }

    // ---- S = H @ PHt + R  (mn at f4 576 = float2 index 1152) ----
    float A[16];
    {
        float Lr[10];
        const float2* s2 = reinterpret_cast<const float2*>(sm);
        #pragma unroll
        for (int v = 0; v < 5; v++) {
            float2 x = s2[1152 + lane * 5 + v];
            Lr[2*v] = x.x; Lr[2*v+1] = x.y;
        }
        #pragma unroll
        for (int i = 0; i < 4; i++) {
            #pragma unroll
            for (int j = 0; j < 4; j++) {
                float a = 0.f;
                #pragma unroll
                for (int k = 0; k <= ((i < j) ? i : j); k++)
                    a += Lr[i*(i+1)/2 + k] * Lr[j*(j+1)/2 + k];
                #pragma unroll
                for (int k = 0; k < 8; k++) a += Hm[i*8+k] * PHt[k*4+j];
                A[i*4+j] = a;
            }
        }
    }

    // ---- Gauss-Jordan solve S X = [PHt^T | res] ----
    float Rh[36];
    #pragma unroll
    for (int r = 0; r < 4; r++) {
        #pragma unroll
        for (int c = 0; c < 8; c++) Rh[r*9+c] = PHt[c*4+r];
        Rh[r*9+8] = res[r];
    }
    #pragma unroll
    for (int c = 0; c < 4; c++) {
        float inv = 1.0f / A[c*4+c];
        #pragma unroll
        for (int j = 0; j < 4; j++) A[c*4+j] *= inv;
        #pragma unroll
        for (int j = 0; j < 9; j++) Rh[c*9+j] *= inv;
        #pragma unroll
        for (int r = 0; r < 4; r++) {
            if (r == c) continue;
            float f = A[r*4+c];
            #pragma unroll
            for (int j = 0; j < 4; j++) A[r*4+j] -= f * A[c*4+j];
            #pragma unroll
            for (int j = 0; j < 9; j++) Rh[r*9+j] -= f * Rh[c*9+j];
        }
    }

    // ---- upd_state ----
    float us[8];
    #pragma unroll
    for (int i = 0; i < 8; i++) {
        float a = ns[i];
        #pragma unroll
        for (int j = 0; j < 4; j++) a += PHt[i*4+j] * Rh[j*9+8];
        us[i] = a;
    }

    // ---- small outputs: direct coalesced STG ----
    reinterpret_cast<float4*>(o_pred)[b] = make_float4(pred[0], pred[1], pred[2], pred[3]);
    {
        float4* s4o = reinterpret_cast<float4*>(o_state) + (size_t)b * 2;
        s4o[0] = make_float4(us[0], us[1], us[2], us[3]);
        s4o[1] = make_float4(us[4], us[5], us[6], us[7]);
    }

    // ---- upd_cov = P' - PHt X (tri); stage padded, compress, bulk store ----
    float UC[36];
    #pragma unroll
    for (int i = 0; i < 8; i++) {
        #pragma unroll
        for (int l = 0; l <= i; l++) {
            float a = Pp[i*(i+1)/2 + l];
            #pragma unroll
            for (int j = 0; j < 4; j++) a -= PHt[i*4+j] * Rh[j*9+l];
            UC[i*(i+1)/2 + l] = a;
        }
    }
    __syncwarp();   // all lanes done reading H/pn/mn smem
    #pragma unroll
    for (int v = 0; v < 16; v++) {
        int e = 4*v;
        s4m[lane * 17 + v] = make_float4(
            psym(UC, (e+0) >> 3, (e+0) & 7),
            psym(UC, (e+1) >> 3, (e+1) & 7),
            psym(UC, (e+2) >> 3, (e+2) & 7),
            psym(UC, (e+3) >> 3, (e+3) & 7));
    }
    __syncwarp();
    {
        float4 t[8];
        #pragma unroll
        for (int k = 0; k < 8; k++) {
            int g = lane + 32*k;
            t[k] = s4m[(g >> 4) * 17 + (g & 15)];
        }
        __syncwarp();
        #pragma unroll
        for (int k = 0; k < 8; k++) s4m[lane + 32*k] = t[k];
        __syncwarp();
        #pragma unroll
        for (int k = 0; k < 8; k++) {
            int g = 256 + lane + 32*k;
            t[k] = s4m[(g >> 4) * 17 + (g & 15)];
        }
        __syncwarp();
        #pragma unroll
        for (int k = 0; k < 8; k++) s4m[256 + lane + 32*k] = t[k];
        __syncwarp();
    }
    asm volatile("fence.proxy.async.shared::cta;" ::: "memory");
    if (lane == 0) {
        bulk_s2g(o_cov + (size_t)wb * 64, smb, 8192);
        asm volatile("cp.async.bulk.commit_group;" ::: "memory");
        asm volatile("cp.async.bulk.wait_group 0;" ::: "memory");
    }
}

extern "C" void kernel_launch(void* const* d_in, const int* in_sizes, int n_in,
                              void* d_out, int out_size)
{
    const float* g_meas = (const float*)d_in[0];
    const float* g_state = (const float*)d_in[1];
    const float* g_cov  = (const float*)d_in[2];
    const float* g_F    = (const float*)d_in[3];
    const float* g_H    = (const float*)d_in[4];
    const float* g_pn   = (const float*)d_in[5];
    const float* g_mn   = (const float*)d_in[6];

    int B = in_sizes[0] / 4;   // measurement is (B, 4)

    float* o_pred  = (float*)d_out;
    float* o_state = o_pred + (size_t)B * 4;
    float* o_cov   = o_state + (size_t)B * 8;

    int blocks = (B + 31) / 32;
    ekf_kernel<<<blocks, 32>>>(g_meas, g_state, g_cov, g_F, g_H, g_pn, g_mn,
                               o_pred, o_state, o_cov, B);
}

// round 15
// speedup vs baseline: 1.0984x; 1.0984x over previous
#include <cuda_runtime.h>

// EKF cell: B=262144, N=8, M=4. One thread/batch, one warp/CTA (32 batches).
// Round-15 = round-13 (champion: two-phase TMA, 12 warps/SM, F+P-only L2
// prefetch @ AHEAD=512) + two micro-opts:
//  * single-pass pad-repack (16-f4 register staging) -- halves syncwarps and
//    lets phase-2 TMA issue earlier (repack is on the critical path between
//    phase-1 wait and phase-2 issue)
//  * prefetch issued from lane 1, demand TMA from lane 0 (no serialization)
// R14's tier-2 prefetch REGRESSED (footprint monotone: 8MB=49.6 < 15MB=51.3
// < tiered=52.3 in-kernel) -- phase-2 is covered by compute; do not prefetch it.

#define OFF_P_F4   544       // P padded region base (f4)
#define OFF_MB_FLT 4352      // mbarrier (float offset, 16B aligned)
#define SM_FLOATS  4356
#define TX1 16384u           // F 8192 + P 8192
#define TX2 9984u            // H 4096 + pn 4608 + mn 1280
#define PN_F4 288            // pn base (f4): 288..575
#define MN_F4 576            // mn base (f4): 576..655
#define AHEAD 512            // ~0.29 waves: 8MB window, ~3.7us lead

__device__ __forceinline__ float psym(const float* t, int i, int j) {
    return (i >= j) ? t[i*(i+1)/2 + j] : t[j*(j+1)/2 + i];
}

__device__ __forceinline__ unsigned sptr(const void* p) {
    return (unsigned)__cvta_generic_to_shared(p);
}

__device__ __forceinline__ void bulk_g2s(unsigned dst, const void* src,
                                         unsigned bytes, unsigned mbar) {
    asm volatile(
        "cp.async.bulk.shared::cluster.global.mbarrier::complete_tx::bytes [%0], [%1], %2, [%3];"
        :: "r"(dst), "l"(src), "r"(bytes), "r"(mbar) : "memory");
}

__device__ __forceinline__ void bulk_s2g(void* dst, unsigned src, unsigned bytes) {
    asm volatile(
        "cp.async.bulk.global.shared::cta.bulk_group [%0], [%1], %2;"
        :: "l"(dst), "r"(src), "r"(bytes) : "memory");
}

__device__ __forceinline__ void l2_prefetch(const void* src, unsigned bytes) {
    asm volatile("cp.async.bulk.prefetch.L2.global [%0], %1;"
                 :: "l"(src), "r"(bytes) : "memory");
}

__device__ __forceinline__ void mbar_wait(unsigned mbar, int parity) {
    asm volatile(
        "{\n\t"
        ".reg .pred P;\n"
        "W%=:\n\t"
        "mbarrier.try_wait.parity.shared.b64 P, [%0], %1;\n\t"
        "@!P bra W%=;\n\t"
        "}"
        :: "r"(mbar), "r"(parity) : "memory");
}

__global__ __launch_bounds__(32, 12) void ekf_kernel(
    const float* __restrict__ g_meas,
    const float* __restrict__ g_state,
    const float* __restrict__ g_cov,
    const float* __restrict__ g_F,
    const float* __restrict__ g_H,
    const float* __restrict__ g_pn,
    const float* __restrict__ g_mn,
    float* __restrict__ o_pred,
    float* __restrict__ o_state,
    float* __restrict__ o_cov,
    int B)
{
    __shared__ __align__(16) float sm[SM_FLOATS];
    float4* s4m = reinterpret_cast<float4*>(sm);

    const int lane = threadIdx.x;
    int wb = blockIdx.x * 32;
    if (wb + 32 > B) wb = B - 32;   // clamp tail: duplicate identical work
    const int b = wb + lane;

    const unsigned smb  = sptr(sm);
    const unsigned mbar = smb + OFF_MB_FLT * 4;

    // ---------- phase 1: TMA F + P (demand on lane 0, prefetch on lane 1) ----
    if (lane == 0) {
        asm volatile("mbarrier.init.shared.b64 [%0], 1;" :: "r"(mbar) : "memory");
    }
    __syncwarp();
    if (lane == 0) {
        asm volatile("fence.proxy.async.shared::cta;" ::: "memory");
        asm volatile("mbarrier.arrive.expect_tx.shared.b64 _, [%0], %1;"
                     :: "r"(mbar), "r"(TX1) : "memory");
        bulk_g2s(smb,                  g_F   + (size_t)wb * 64, 8192, mbar);
        bulk_g2s(smb + OFF_P_F4 * 16,  g_cov + (size_t)wb * 64, 8192, mbar);
    } else if (lane == 1) {
        // L2 prefetch of phase-1 inputs for the CTA ~3.7us behind us
        int pwb = (blockIdx.x + AHEAD) * 32;
        if (pwb + 32 <= B) {
            l2_prefetch(g_F   + (size_t)pwb * 64, 8192);
            l2_prefetch(g_cov + (size_t)pwb * 64, 8192);
        }
    }

    // overlap: small direct loads
    float mea[4], st[8];
    {
        float4 mv = reinterpret_cast<const float4*>(g_meas)[b];
        mea[0] = mv.x; mea[1] = mv.y; mea[2] = mv.z; mea[3] = mv.w;
        const float4* s4 = reinterpret_cast<const float4*>(g_state) + (size_t)b * 2;
        float4 a = s4[0], c = s4[1];
        st[0]=a.x; st[1]=a.y; st[2]=a.z; st[3]=a.w;
        st[4]=c.x; st[5]=c.y; st[6]=c.z; st[7]=c.w;
    }

    mbar_wait(mbar, 0);
    __syncwarp();

    // ---------- single-pass pad-repack F and P: stride 16 -> 17 f4 ----------
    #pragma unroll
    for (int base = OFF_P_F4; base >= 0; base -= OFF_P_F4) {  // P then F
        float4 t[16];
        #pragma unroll
        for (int k = 0; k < 16; k++) t[k] = s4m[base + lane + 32*k];
        __syncwarp();
        #pragma unroll
        for (int k = 0; k < 16; k++) {
            int g = lane + 32*k;
            s4m[base + (g >> 4) * 17 + (g & 15)] = t[k];
        }
        __syncwarp();
    }

    // ---------- unpack F (64 regs) and P (tri 36 regs) ----------
    float Fm[64];
    #pragma unroll
    for (int v = 0; v < 16; v++) {
        float4 x = s4m[lane * 17 + v];
        Fm[4*v+0] = x.x; Fm[4*v+1] = x.y; Fm[4*v+2] = x.z; Fm[4*v+3] = x.w;
    }
    float Pt[36];
    #pragma unroll
    for (int v = 0; v < 16; v++) {
        float4 x = s4m[OFF_P_F4 + lane * 17 + v];
        float vals[4] = {x.x, x.y, x.z, x.w};
        #pragma unroll
        for (int c = 0; c < 4; c++) {
            int e = 4*v + c, i = e >> 3, j = e & 7;
            if (i >= j) Pt[i*(i+1)/2 + j] = vals[c];
        }
    }
    __syncwarp();   // all lanes done reading F/P smem

    // ---------- phase 2: TMA H / pn / mn into now-dead smem ----------
    if (lane == 0) {
        asm volatile("fence.proxy.async.shared::cta;" ::: "memory");
        asm volatile("mbarrier.arrive.expect_tx.shared.b64 _, [%0], %1;"
                     :: "r"(mbar), "r"(TX2) : "memory");
        bulk_g2s(smb,              g_H  + (size_t)wb * 32, 4096, mbar);
        bulk_g2s(smb + PN_F4 * 16, g_pn + (size_t)wb * 36, 4608, mbar);
        bulk_g2s(smb + MN_F4 * 16, g_mn + (size_t)wb * 10, 1280, mbar);
    }

    // ---- compute overlapped with phase-2 TMA ----
    float ns[8];
    #pragma unroll
    for (int i = 0; i < 8; i++) {
        float a = 0.f;
        #pragma unroll
        for (int j = 0; j < 8; j++) a += Fm[i*8+j] * st[j];
        ns[i] = a;
    }
    // P' = F P F^T (column-strip, lower tri)
    float Pp[36];
    #pragma unroll
    for (int l = 0; l < 8; l++) {
        float g[8];
        #pragma unroll
        for (int j = 0; j < 8; j++) {
            float a = 0.f;
            #pragma unroll
            for (int k = 0; k < 8; k++) a += psym(Pt, j, k) * Fm[l*8+k];
            g[j] = a;
        }
        #pragma unroll
        for (int i = l; i < 8; i++) {
            float a = 0.f;
            #pragma unroll
            for (int j = 0; j < 8; j++) a += Fm[i*8+j] * g[j];
            Pp[i*(i+1)/2 + l] = a;
        }
    }
    // Fm, Pt dead.

    mbar_wait(mbar, 1);
    __syncwarp();

    // ---- single-pass repack H: stride 8 -> 9 f4 ----
    {
        float4 t[8];
        #pragma unroll
        for (int k = 0; k < 8; k++) t[k] = s4m[lane + 32*k];
        __syncwarp();
        #pragma unroll
        for (int k = 0; k < 8; k++) {
            int g = lane + 32*k;
            s4m[(g >> 3) * 9 + (g & 7)] = t[k];
        }
        __syncwarp();
    }

    // ---- P' += Q = Lq Lq^T ----
    {
        float Lq[36];
        #pragma unroll
        for (int v = 0; v < 9; v++) {
            float4 x = s4m[PN_F4 + lane * 9 + v];
            Lq[4*v+0] = x.x; Lq[4*v+1] = x.y; Lq[4*v+2] = x.z; Lq[4*v+3] = x.w;
        }
        #pragma unroll
        for (int i = 0; i < 8; i++) {
            #pragma unroll
            for (int l = 0; l <= i; l++) {
                float a = Pp[i*(i+1)/2 + l];
                #pragma unroll
                for (int k = 0; k <= l; k++)
                    a += Lq[i*(i+1)/2 + k] * Lq[l*(l+1)/2 + k];
                Pp[i*(i+1)/2 + l] = a;
            }
        }
    }

    // ---- H; prediction & residual ----
    float Hm[32];
    #pragma unroll
    for (int v = 0; v < 8; v++) {
        float4 x = s4m[lane * 9 + v];
        Hm[4*v+0] = x.x; Hm[4*v+1] = x.y; Hm[4*v+2] = x.z; Hm[4*v+3] = x.w;
    }
    float pred[4], res[4];
    #pragma unroll
    for (int i = 0; i < 4; i++) {
        float a = 0.f;
        #pragma unroll
        for (int j = 0; j < 8; j++) a += Hm[i*8+j] * ns[j];
        pred[i] = a;
        res[i] = mea[i] - a;
    }

    // ---- PHt = P' @ H^T ----
    float PHt[32];
    #pragma unroll
    for (int i = 0; i < 8; i++) {
        #pragma unroll
        for (int j = 0; j < 4; j++) {
            float a = 0.f;
            #pragma unroll
            for (int k = 0; k < 8; k++) a += psym(Pp, i, k) * Hm[j*8+k];
            PHt[i*4+j] = a;
        }
    }

    // ---- S = H @ PHt + R  (mn at f4 576 = float2 index 1152) ----
    float A[16];
    {
        float Lr[10];
        const float2* s2 = reinterpret_cast<const float2*>(sm);
        #pragma unroll
        for (int v = 0; v < 5; v++) {
            float2 x = s2[1152 + lane * 5 + v];
            Lr[2*v] = x.x; Lr[2*v+1] = x.y;
        }
        #pragma unroll
        for (int i = 0; i < 4; i++) {
            #pragma unroll
            for (int j = 0; j < 4; j++) {
                float a = 0.f;
                #pragma unroll
                for (int k = 0; k <= ((i < j) ? i : j); k++)
                    a += Lr[i*(i+1)/2 + k] * Lr[j*(j+1)/2 + k];
                #pragma unroll
                for (int k = 0; k < 8; k++) a += Hm[i*8+k] * PHt[k*4+j];
                A[i*4+j] = a;
            }
        }
    }

    // ---- Gauss-Jordan solve S X = [PHt^T | res] ----
    float Rh[36];
    #pragma unroll
    for (int r = 0; r < 4; r++) {
        #pragma unroll
        for (int c = 0; c < 8; c++) Rh[r*9+c] = PHt[c*4+r];
        Rh[r*9+8] = res[r];
    }
    #pragma unroll
    for (int c = 0; c < 4; c++) {
        float inv = 1.0f / A[c*4+c];
        #pragma unroll
        for (int j = 0; j < 4; j++) A[c*4+j] *= inv;
        #pragma unroll
        for (int j = 0; j < 9; j++) Rh[c*9+j] *= inv;
        #pragma unroll
        for (int r = 0; r < 4; r++) {
            if (r == c) continue;
            float f = A[r*4+c];
            #pragma unroll
            for (int j = 0; j < 4; j++) A[r*4+j] -= f * A[c*4+j];
            #pragma unroll
            for (int j = 0; j < 9; j++) Rh[r*9+j] -= f * Rh[c*9+j];
        }
    }

    // ---- upd_state ----
    float us[8];
    #pragma unroll
    for (int i = 0; i < 8; i++) {
        float a = ns[i];
        #pragma unroll
        for (int j = 0; j < 4; j++) a += PHt[i*4+j] * Rh[j*9+8];
        us[i] = a;
    }

    // ---- small outputs: direct coalesced STG ----
    reinterpret_cast<float4*>(o_pred)[b] = make_float4(pred[0], pred[1], pred[2], pred[3]);
    {
        float4* s4o = reinterpret_cast<float4*>(o_state) + (size_t)b * 2;
        s4o[0] = make_float4(us[0], us[1], us[2], us[3]);
        s4o[1] = make_float4(us[4], us[5], us[6], us[7]);
    }

    // ---- upd_cov = P' - PHt X (tri); stage padded, compress, bulk store ----
    float UC[36];
    #pragma unroll
    for (int i = 0; i < 8; i++) {
        #pragma unroll
        for (int l = 0; l <= i; l++) {
            float a = Pp[i*(i+1)/2 + l];
            #pragma unroll
            for (int j = 0; j < 4; j++) a -= PHt[i*4+j] * Rh[j*9+l];
            UC[i*(i+1)/2 + l] = a;
        }
    }
    __syncwarp();   // all lanes done reading H/pn/mn smem
    #pragma unroll
    for (int v = 0; v < 16; v++) {
        int e = 4*v;
        s4m[lane * 17 + v] = make_float4(
            psym(UC, (e+0) >> 3, (e+0) & 7),
            psym(UC, (e+1) >> 3, (e+1) & 7),
            psym(UC, (e+2) >> 3, (e+2) & 7),
            psym(UC, (e+3) >> 3, (e+3) & 7));
    }
    __syncwarp();
    // single-pass compress padded (17) -> linear (16)
    {
        float4 t[16];
        #pragma unroll
        for (int k = 0; k < 16; k++) {
            int g = lane + 32*k;
            t[k] = s4m[(g >> 4) * 17 + (g & 15)];
        }
        __syncwarp();
        #pragma unroll
        for (int k = 0; k < 16; k++) s4m[lane + 32*k] = t[k];
        __syncwarp();
    }
    asm volatile("fence.proxy.async.shared::cta;" ::: "memory");
    if (lane == 0) {
        bulk_s2g(o_cov + (size_t)wb * 64, smb, 8192);
        asm volatile("cp.async.bulk.commit_group;" ::: "memory");
        asm volatile("cp.async.bulk.wait_group 0;" ::: "memory");
    }
}

extern "C" void kernel_launch(void* const* d_in, const int* in_sizes, int n_in,
                              void* d_out, int out_size)
{
    const float* g_meas = (const float*)d_in[0];
    const float* g_state = (const float*)d_in[1];
    const float* g_cov  = (const float*)d_in[2];
    const float* g_F    = (const float*)d_in[3];
    const float* g_H    = (const float*)d_in[4];
    const float* g_pn   = (const float*)d_in[5];
    const float* g_mn   = (const float*)d_in[6];

    int B = in_sizes[0] / 4;   // measurement is (B, 4)

    float* o_pred  = (float*)d_out;
    float* o_state = o_pred + (size_t)B * 4;
    float* o_cov   = o_state + (size_t)B * 8;

    int blocks = (B + 31) / 32;
    ekf_kernel<<<blocks, 32>>>(g_meas, g_state, g_cov, g_F, g_H, g_pn, g_mn,
                               o_pred, o_state, o_cov, B);
}